// round 15
// baseline (speedup 1.0000x reference)
#include <cuda_runtime.h>
#include <cuda_fp16.h>
#include <cstdint>

#define B_ 8
#define H_ 128
#define W_ 128
#define C_ 256
#define OC_ 512
#define KTOT_ 2304   // 9 taps * 256
#define S_ 3         // pipeline stages

// ---------------- static device scratch (no allocs) ----------------
// Offsets pair-packed: g_offp[(b*128+ip)*64 + jl]*512 + ch] = {conv[2jl][ch], conv[2jl+1][ch]}
__device__ __align__(16) uint32_t g_offp[(size_t)B_ * H_ * 64 * OC_];
__device__ __align__(16) __half g_xh[(size_t)B_ * H_ * W_ * C_];    // x in f16
__device__ __align__(16) __half g_wT[(size_t)OC_ * KTOT_];          // W^T [n][k] f16

// ---------------- helpers ----------------
__device__ __forceinline__ uint32_t smem_u32(const void* p) {
    uint32_t a;
    asm("{ .reg .u64 t; cvta.to.shared.u64 t, %1; cvt.u32.u64 %0, t; }"
        : "=r"(a) : "l"(p));
    return a;
}

#define CP16(dst, src, sz) \
    asm volatile("cp.async.cg.shared.global [%0], [%1], 16, %2;" \
                 :: "r"(dst), "l"(src), "r"(sz))
#define CP_COMMIT() asm volatile("cp.async.commit_group;" ::: "memory")

#define LDSM4(r0, r1, r2, r3, a) \
    asm volatile("ldmatrix.sync.aligned.m8n8.x4.shared.b16 {%0,%1,%2,%3}, [%4];" \
                 : "=r"(r0), "=r"(r1), "=r"(r2), "=r"(r3) : "r"(a))

#define MMA16816(c, a, b0, b1) \
    asm volatile("mma.sync.aligned.m16n8k16.row.col.f32.f16.f16.f32 " \
                 "{%0,%1,%2,%3}, {%4,%5,%6,%7}, {%8,%9}, {%0,%1,%2,%3};" \
                 : "+f"((c)[0]), "+f"((c)[1]), "+f"((c)[2]), "+f"((c)[3]) \
                 : "r"((a)[0]), "r"((a)[1]), "r"((a)[2]), "r"((a)[3]), \
                   "r"(b0), "r"(b1))

// L2-only 32-bit load (streaming, no L1 allocation)
__device__ __forceinline__ uint32_t ldcg_u32(const uint32_t* p) {
    uint32_t v;
    asm volatile("ld.global.cg.u32 %0, [%1];" : "=r"(v) : "l"(p));
    return v;
}

// ---------------- fp32 -> fp16 conversion kernels ----------------
__global__ void __launch_bounds__(256) conv_x_f16(const float* __restrict__ x) {
    const size_t i = (size_t)blockIdx.x * 256 + threadIdx.x;  // per 8 floats
    const float4* xv = (const float4*)x;
    float4 v0 = xv[i * 2], v1 = xv[i * 2 + 1];
    __half2 h0 = __floats2half2_rn(v0.x, v0.y);
    __half2 h1 = __floats2half2_rn(v0.z, v0.w);
    __half2 h2 = __floats2half2_rn(v1.x, v1.y);
    __half2 h3 = __floats2half2_rn(v1.z, v1.w);
    uint4 o;
    o.x = *reinterpret_cast<uint32_t*>(&h0);
    o.y = *reinterpret_cast<uint32_t*>(&h1);
    o.z = *reinterpret_cast<uint32_t*>(&h2);
    o.w = *reinterpret_cast<uint32_t*>(&h3);
    ((uint4*)g_xh)[i] = o;
}

__global__ void __launch_bounds__(256) conv_w_f16(const float* __restrict__ w) {
    const int idx = blockIdx.x * 256 + threadIdx.x;  // 512 * 288 = 147456
    const int n  = idx / 288;
    const int kc = idx - n * 288;
    __align__(16) __half h[8];
#pragma unroll
    for (int t = 0; t < 8; ++t)
        h[t] = __float2half_rn(w[(size_t)(kc * 8 + t) * OC_ + n]);
    *(uint4*)(g_wT + (size_t)n * KTOT_ + kc * 8) = *(const uint4*)h;
}

// ---------------- HMMA implicit-GEMM conv ----------------
// CTA: 256 threads (8 warps, 2M x 4N), tile M=128 x N=128, warp tile 64x32.
// K-chunk=64, 36 iters, 3-stage cp.async ring, one barrier/iter (rolled loop).
// smem rows padded 64->72 halfs (144B): conflict-free ldmatrix.
// Epilogue staged through smem, pair-interleaved, dense STG.128 of g_offp.
#define ROWPAD 72
#define T_IDX(st, r, c) (((st) * 128 + (r)) * ROWPAD + (c))
#define ARR_HALFS (S_ * 128 * ROWPAD)
#define SMEM_BYTES (2 * ARR_HALFS * 2)     // A + B, fp16  (= 110,592 B)
#define EPI_PITCH 136

__global__ void __launch_bounds__(256, 2)
conv_hmma(const float* __restrict__ bias) {
    extern __shared__ __half sm[];
    __half* As = sm;
    __half* Bs = sm + ARR_HALFS;

    const int tid  = threadIdx.x;
    const int mt   = blockIdx.y;          // b*128 + conv row ip
    const int n0   = blockIdx.x * 128;    // out-channel tile
    const int b    = mt >> 7;
    const int irow = mt & 127;
    const __half* xb = g_xh + (size_t)b * (H_ * W_ * C_);

    auto load_stage = [&](int st, int kt) {
        if (kt < 36) {
            const int tap = kt >> 2;              // 4 k-chunks per tap (K=64)
            const int di  = tap / 3;
            const int dj  = tap - 3 * di;
            const int ii  = irow + di - 1;
            const bool rowok = ((unsigned)ii < 128u);
            const int c0  = (kt & 3) * 64;
            // A: 128 rows x 8 chunks = 1024 cp ops (4/thread)
#pragma unroll
            for (int it = 0; it < 4; ++it) {
                const int ch = it * 256 + tid;
                const int r  = ch >> 3;
                const int kc = ch & 7;
                const int jj = r + dj - 1;
                const __half* ga = xb;
                int sz = 0;
                if (rowok && (unsigned)jj < 128u) {
                    ga = xb + ((size_t)ii * 128 + jj) * 256 + c0 + kc * 8;
                    sz = 16;
                }
                CP16(smem_u32(&As[T_IDX(st, r, kc * 8)]), ga, sz);
            }
            // B: 128 rows x 8 chunks = 1024 cp ops (4/thread)
#pragma unroll
            for (int it = 0; it < 4; ++it) {
                const int ch = it * 256 + tid;
                const int r  = ch >> 3;
                const int kc = ch & 7;
                const __half* gb = g_wT + (size_t)(n0 + r) * KTOT_ + kt * 64 + kc * 8;
                CP16(smem_u32(&Bs[T_IDX(st, r, kc * 8)]), gb, 16);
            }
        }
        CP_COMMIT();   // uniform group accounting (empty beyond 36)
    };

    load_stage(0, 0);
    load_stage(1, 1);

    const int warp = tid >> 5;
    const int lane = tid & 31;
    const int wm = (warp >> 2) * 64;   // 2 warps in M
    const int wn = (warp & 3) * 32;    // 4 warps in N

    float acc[4][4][4] = {};

    for (int kt = 0; kt < 36; ++kt) {
        const int s = kt % S_;
        asm volatile("cp.async.wait_group 1;" ::: "memory");  // stage kt resident
        __syncthreads();                                       // compute of kt-1 done
        load_stage((kt + 2) % S_, kt + 2);                     // overlaps MMAs below

#pragma unroll
        for (int ks = 0; ks < 4; ++ks) {
            uint32_t a[4][4], bf[2][4];
#pragma unroll
            for (int mf = 0; mf < 4; ++mf)
                LDSM4(a[mf][0], a[mf][1], a[mf][2], a[mf][3],
                      smem_u32(&As[T_IDX(s, wm + mf * 16 + (lane & 15),
                                         ks * 16 + (lane >> 4) * 8)]));
#pragma unroll
            for (int nf2 = 0; nf2 < 2; ++nf2)
                LDSM4(bf[nf2][0], bf[nf2][1], bf[nf2][2], bf[nf2][3],
                      smem_u32(&Bs[T_IDX(s, wn + nf2 * 16 + (lane & 7) + ((lane >> 4) << 3),
                                         ks * 16 + ((lane >> 3) & 1) * 8)]));
#pragma unroll
            for (int mf = 0; mf < 4; ++mf)
#pragma unroll
                for (int nf = 0; nf < 4; ++nf)
                    MMA16816(acc[mf][nf], a[mf],
                             bf[nf >> 1][(nf & 1) * 2],
                             bf[nf >> 1][(nf & 1) * 2 + 1]);
        }
    }
    asm volatile("cp.async.wait_all;" ::: "memory");
    __syncthreads();   // pipeline smem dead; reuse for epilogue staging

    // ---- epilogue: +bias, fp16, stage tile [128 pos][128 ch] to smem ----
#pragma unroll
    for (int mf = 0; mf < 4; ++mf) {
        const int m0 = wm + mf * 16 + (lane >> 2);
#pragma unroll
        for (int nf = 0; nf < 4; ++nf) {
            const int cl = wn + nf * 8 + (lane & 3) * 2;
            const float b0v = bias[n0 + cl], b1v = bias[n0 + cl + 1];
            __half2 v0 = __floats2half2_rn(acc[mf][nf][0] + b0v, acc[mf][nf][1] + b1v);
            __half2 v1 = __floats2half2_rn(acc[mf][nf][2] + b0v, acc[mf][nf][3] + b1v);
            *(__half2*)&sm[(size_t)m0 * EPI_PITCH + cl]       = v0;
            *(__half2*)&sm[(size_t)(m0 + 8) * EPI_PITCH + cl] = v1;
        }
    }
    __syncthreads();

    // ---- pair-interleaved dense write-out ----
    // pair[jl][ch] = {tile[2jl][ch], tile[2jl+1][ch]} as __half2 (uint32).
    // 64 jl x 128 ch = 8192 uint32 = 2048 uint4; 8 per thread, STG.128.
    const size_t pbase = (size_t)mt * 64 * OC_ + n0;   // uint32 index
#pragma unroll
    for (int it = 0; it < 8; ++it) {
        const int idx = it * 256 + tid;
        const int jl = idx >> 5;          // 0..63
        const int u  = idx & 31;          // 0..31 -> channels 4u..4u+3
        const uint2 lo = *(const uint2*)&sm[(size_t)(2 * jl)     * EPI_PITCH + 4 * u];
        const uint2 hi = *(const uint2*)&sm[(size_t)(2 * jl + 1) * EPI_PITCH + 4 * u];
        uint4 o;
        o.x = __byte_perm(lo.x, hi.x, 0x5410);
        o.y = __byte_perm(lo.x, hi.x, 0x7632);
        o.z = __byte_perm(lo.y, hi.y, 0x5410);
        o.w = __byte_perm(lo.y, hi.y, 0x7632);
        *(uint4*)(g_offp + pbase + (size_t)jl * OC_ + 4 * u) = o;
    }
}

// ---------------- deformable sampling (keras reshape remap) ----------------
// One packed L2-only 4B load yields both offsets.
// floor via cvt.rmi; ceil -> min(lt+1,127): exact (frac=0 cancels the corner).
__device__ __forceinline__ float sample_one(int b, int i, int j, int q) {
    const int delta = (i >= 64) ? 1 : 0;
    const int ip    = 2 * (i & 63) + ((j >= 64) ? 1 : 0);
    const int jl    = j & 63;

    const uint32_t pk = ldcg_u32(
        g_offp + (((size_t)(b * H_ + ip)) * 64 + jl) * OC_ + 2 * q + delta);
    const __half2 ph = *reinterpret_cast<const __half2*>(&pk);
    const float off0 = __low2float(ph);
    const float off1 = __high2float(ph);

    float c0 = fminf(fmaxf(off0 + (float)i, 0.f), 127.f);
    float c1 = fminf(fmaxf(off1 + (float)j, 0.f), 127.f);

    const int lt0 = __float2int_rd(c0);
    const int lt1 = __float2int_rd(c1);
    const float fr0 = c0 - (float)lt0;
    const float fr1 = c1 - (float)lt1;
    const int rb0 = min(lt0 + 1, 127);
    const int rb1 = min(lt1 + 1, 127);

    const __half* xq = g_xh + (size_t)b * (H_ * W_ * C_) + q;
    const float v_lt = __half2float(__ldg(xq + (size_t)(lt0 * W_ + lt1) * C_));
    const float v_rb = __half2float(__ldg(xq + (size_t)(rb0 * W_ + rb1) * C_));
    const float v_lb = __half2float(__ldg(xq + (size_t)(lt0 * W_ + rb1) * C_));
    const float v_rt = __half2float(__ldg(xq + (size_t)(rb0 * W_ + lt1) * C_));

    const float vt = v_lt + (v_rt - v_lt) * fr0;
    const float vb = v_lb + (v_rb - v_lb) * fr0;
    return vt + (vb - vt) * fr1;
}

// 4 spatial positions per block -> 4 independent load chains (MLP x4).
__global__ void sample_kernel(float* __restrict__ out) {
    const int q    = threadIdx.x;
    const int bij0 = blockIdx.x * 4;          // j0 multiple of 4
    const int j0   = bij0 & 127;
    const int i    = (bij0 >> 7) & 127;
    const int b    = bij0 >> 14;

    float r[4];
#pragma unroll
    for (int t = 0; t < 4; ++t)
        r[t] = sample_one(b, i, j0 + t, q);
#pragma unroll
    for (int t = 0; t < 4; ++t)
        out[(size_t)(bij0 + t) * C_ + q] = r[t];
}

// ---------------- launch ----------------
extern "C" void kernel_launch(void* const* d_in, const int* in_sizes, int n_in,
                              void* d_out, int out_size) {
    const float* x    = (const float*)d_in[0];   // (8,128,128,256) f32
    const float* wgt  = (const float*)d_in[1];   // (3,3,256,512)  f32
    const float* bias = (const float*)d_in[2];   // (512,)         f32
    float* out = (float*)d_out;

    conv_x_f16<<<16384, 256>>>(x);
    conv_w_f16<<<576, 256>>>(wgt);

    cudaFuncSetAttribute(conv_hmma,
                         cudaFuncAttributeMaxDynamicSharedMemorySize, SMEM_BYTES);
    conv_hmma<<<dim3(4, 1024), 256, SMEM_BYTES>>>(bias);

    sample_kernel<<<(B_ * H_ * W_) / 4, 256>>>(out);
}

// round 16
// speedup vs baseline: 1.0808x; 1.0808x over previous
#include <cuda_runtime.h>
#include <cuda_fp16.h>
#include <cstdint>

#define B_ 8
#define H_ 128
#define W_ 128
#define C_ 256
#define OC_ 512
#define KTOT_ 2304   // 9 taps * 256

// ---------------- static device scratch (no allocs) ----------------
__device__ __align__(16) __half g_off[(size_t)B_ * H_ * W_ * OC_];  // conv out (fp16)
__device__ __align__(16) __half g_xh[(size_t)B_ * H_ * W_ * C_];    // x in f16
__device__ __align__(16) __half g_wT[(size_t)OC_ * KTOT_];          // W^T [n][k] f16

// ---------------- helpers ----------------
__device__ __forceinline__ uint32_t smem_u32(const void* p) {
    uint32_t a;
    asm("{ .reg .u64 t; cvta.to.shared.u64 t, %1; cvt.u32.u64 %0, t; }"
        : "=r"(a) : "l"(p));
    return a;
}

#define CP16(dst, src, sz) \
    asm volatile("cp.async.cg.shared.global [%0], [%1], 16, %2;" \
                 :: "r"(dst), "l"(src), "r"(sz))
#define CP_COMMIT() asm volatile("cp.async.commit_group;" ::: "memory")

#define LDSM4(r0, r1, r2, r3, a) \
    asm volatile("ldmatrix.sync.aligned.m8n8.x4.shared.b16 {%0,%1,%2,%3}, [%4];" \
                 : "=r"(r0), "=r"(r1), "=r"(r2), "=r"(r3) : "r"(a))

#define MMA16816(c, a, b0, b1) \
    asm volatile("mma.sync.aligned.m16n8k16.row.col.f32.f16.f16.f32 " \
                 "{%0,%1,%2,%3}, {%4,%5,%6,%7}, {%8,%9}, {%0,%1,%2,%3};" \
                 : "+f"((c)[0]), "+f"((c)[1]), "+f"((c)[2]), "+f"((c)[3]) \
                 : "r"((a)[0]), "r"((a)[1]), "r"((a)[2]), "r"((a)[3]), \
                   "r"(b0), "r"(b1))

// L2-only 16-bit load (streaming, no L1 allocation)
__device__ __forceinline__ __half ldcg_h(const __half* p) {
    unsigned short v;
    asm volatile("ld.global.cg.u16 %0, [%1];" : "=h"(v) : "l"(p));
    return *reinterpret_cast<__half*>(&v);
}

// ---------------- fp32 -> fp16 conversion kernels ----------------
__global__ void __launch_bounds__(256) conv_x_f16(const float* __restrict__ x) {
    const size_t i = (size_t)blockIdx.x * 256 + threadIdx.x;  // per 8 floats
    const float4* xv = (const float4*)x;
    float4 v0 = xv[i * 2], v1 = xv[i * 2 + 1];
    __half2 h0 = __floats2half2_rn(v0.x, v0.y);
    __half2 h1 = __floats2half2_rn(v0.z, v0.w);
    __half2 h2 = __floats2half2_rn(v1.x, v1.y);
    __half2 h3 = __floats2half2_rn(v1.z, v1.w);
    uint4 o;
    o.x = *reinterpret_cast<uint32_t*>(&h0);
    o.y = *reinterpret_cast<uint32_t*>(&h1);
    o.z = *reinterpret_cast<uint32_t*>(&h2);
    o.w = *reinterpret_cast<uint32_t*>(&h3);
    ((uint4*)g_xh)[i] = o;
}

__global__ void __launch_bounds__(256) conv_w_f16(const float* __restrict__ w) {
    const int idx = blockIdx.x * 256 + threadIdx.x;  // 512 * 288 = 147456
    const int n  = idx / 288;
    const int kc = idx - n * 288;
    __align__(16) __half h[8];
#pragma unroll
    for (int t = 0; t < 8; ++t)
        h[t] = __float2half_rn(w[(size_t)(kc * 8 + t) * OC_ + n]);
    *(uint4*)(g_wT + (size_t)n * KTOT_ + kc * 8) = *(const uint4*)h;
}

// ---------------- HMMA implicit-GEMM conv with 3-row band cache ----------
// CTA: 256 threads (8 warps, 2M x 4N), tile M=128 x N=128.
// K loop cc-major: 4 channel-chunks(64) x 9 taps. Band (3 x 130 x 64ch,
// zero-padded halo) loaded once per cc; taps read shifted views (A traffic /2.9).
// B: 3-stage cp.async ring. ONE commit group and ONE barrier per iteration.
// Band sections prefetched 6 iters ahead: t0@tap3, t1@tap6, t2@tap0.
#define ROWPAD 72
#define BAND_HALFS (390 * ROWPAD)               // 3 * 130 rows
#define BS_HALFS (3 * 128 * ROWPAD)
#define SMEM_BYTES ((BAND_HALFS + BS_HALFS) * 2)  // 111,456 B
#define EPI_PITCH 136

__global__ void __launch_bounds__(256, 2)
conv_hmma(const float* __restrict__ bias) {
    extern __shared__ __half sm[];
    __half* Band = sm;                    // [t*130 + (jj+1)][ROWPAD]
    __half* Bs   = sm + BAND_HALFS;       // [stage*128 + n][ROWPAD]

    const int tid  = threadIdx.x;
    const int mt   = blockIdx.y;          // b*128 + image row i
    const int n0   = blockIdx.x * 128;    // out-channel tile
    const int b    = mt >> 7;
    const int irow = mt & 127;
    const __half* xb = g_xh + (size_t)b * (H_ * W_ * C_);

    // Load one band section t (130 rows x 64 ch) for channel chunk cc. No commit.
    auto load_band_t = [&](int cc, int t) {
        if (cc < 4) {
            const int c0 = cc * 64;
            const int ii = irow + t - 1;
            const bool rowok = ((unsigned)ii < 128u);
            const __half* xrow = xb + (size_t)ii * (128 * 256) + c0;
#pragma unroll
            for (int it = 0; it < 5; ++it) {
                const int op = it * 256 + tid;       // 1040 ops
                if (op < 1040) {
                    const int jp = op >> 3;          // 0..129
                    const int kc = op & 7;
                    const int jj = jp - 1;
                    const __half* ga = xb;
                    int sz = 0;
                    if (rowok && (unsigned)jj < 128u) {
                        ga = xrow + (size_t)jj * 256 + kc * 8;
                        sz = 16;
                    }
                    CP16(smem_u32(&Band[(t * 130 + jp) * ROWPAD + kc * 8]), ga, sz);
                }
            }
        }
    };
    // Load B tile for global step g (tap = g%9, cc = g/9). No commit.
    auto load_B = [&](int st, int g) {
        if (g < 36) {
            const int tap = g % 9;
            const int cc  = g / 9;
            const int k0  = tap * 256 + cc * 64;
#pragma unroll
            for (int it = 0; it < 4; ++it) {
                const int ch = it * 256 + tid;
                const int r  = ch >> 3;
                const int kc = ch & 7;
                CP16(smem_u32(&Bs[(st * 128 + r) * ROWPAD + kc * 8]),
                     g_wT + (size_t)(n0 + r) * KTOT_ + k0 + kc * 8, 16);
            }
        }
    };

    // Prologue: full band for cc=0 + B(0) in group 1; B(1) in group 2.
    load_band_t(0, 0);
    load_band_t(0, 1);
    load_band_t(0, 2);
    load_B(0, 0);
    CP_COMMIT();
    load_B(1, 1);
    CP_COMMIT();

    const int warp = tid >> 5;
    const int lane = tid & 31;
    const int wm = (warp >> 2) * 64;   // 2 warps in M
    const int wn = (warp & 3) * 32;    // 4 warps in N

    float acc[4][4][4] = {};

    for (int g = 0; g < 36; ++g) {
        const int s   = g % 3;
        const int tap = g % 9;
        const int cc  = g / 9;
        asm volatile("cp.async.wait_group 1;" ::: "memory");  // group g done
        __syncthreads();                                       // iter g-1 compute done

        // Issue this iteration's loads (one combined commit group):
        load_B((g + 2) % 3, g + 2);
        if (tap == 3) load_band_t(cc + 1, 0);        // t0 free after tap2
        else if (tap == 6) load_band_t(cc + 1, 1);   // t1 free after tap5
        else if (tap == 0 && cc > 0) load_band_t(cc, 2);  // t2 free after prev tap8
        CP_COMMIT();

        const int di = tap / 3;
        const int dj = tap - 3 * di;
        const int abase = di * 130 + dj;             // + j gives band row

#pragma unroll
        for (int ks = 0; ks < 4; ++ks) {
            uint32_t a[4][4], bf[2][4];
#pragma unroll
            for (int mf = 0; mf < 4; ++mf)
                LDSM4(a[mf][0], a[mf][1], a[mf][2], a[mf][3],
                      smem_u32(&Band[(abase + wm + mf * 16 + (lane & 15)) * ROWPAD +
                                     ks * 16 + (lane >> 4) * 8]));
#pragma unroll
            for (int nf2 = 0; nf2 < 2; ++nf2)
                LDSM4(bf[nf2][0], bf[nf2][1], bf[nf2][2], bf[nf2][3],
                      smem_u32(&Bs[(s * 128 + wn + nf2 * 16 + (lane & 7) +
                                    ((lane >> 4) << 3)) * ROWPAD +
                                   ks * 16 + ((lane >> 3) & 1) * 8]));
#pragma unroll
            for (int mf = 0; mf < 4; ++mf)
#pragma unroll
                for (int nf = 0; nf < 4; ++nf)
                    MMA16816(acc[mf][nf], a[mf],
                             bf[nf >> 1][(nf & 1) * 2],
                             bf[nf >> 1][(nf & 1) * 2 + 1]);
        }
    }
    asm volatile("cp.async.wait_all;" ::: "memory");
    __syncthreads();   // smem dead; reuse for epilogue staging

    // ---- epilogue: +bias, fp16, stage to smem, then dense STG.128 ----
#pragma unroll
    for (int mf = 0; mf < 4; ++mf) {
        const int m0 = wm + mf * 16 + (lane >> 2);
#pragma unroll
        for (int nf = 0; nf < 4; ++nf) {
            const int cl = wn + nf * 8 + (lane & 3) * 2;
            const float b0v = bias[n0 + cl], b1v = bias[n0 + cl + 1];
            __half2 v0 = __floats2half2_rn(acc[mf][nf][0] + b0v, acc[mf][nf][1] + b1v);
            __half2 v1 = __floats2half2_rn(acc[mf][nf][2] + b0v, acc[mf][nf][3] + b1v);
            *(__half2*)&sm[(size_t)m0 * EPI_PITCH + cl]       = v0;
            *(__half2*)&sm[(size_t)(m0 + 8) * EPI_PITCH + cl] = v1;
        }
    }
    __syncthreads();

    const size_t rowbase = (size_t)mt * 128 * OC_;
#pragma unroll
    for (int it = 0; it < 8; ++it) {
        const int idx = it * 256 + tid;
        const int m = idx >> 4;
        const int u = idx & 15;
        const uint4 v = *(const uint4*)&sm[(size_t)m * EPI_PITCH + u * 8];
        *(uint4*)(g_off + rowbase + (size_t)m * OC_ + n0 + u * 8) = v;
    }
}

// ---------------- deformable sampling (keras reshape remap) ----------------
__device__ __forceinline__ float sample_one(int b, int i, int j, int q) {
    const int delta = (i >= 64) ? 1 : 0;
    const int ip    = 2 * (i & 63) + ((j >= 64) ? 1 : 0);
    const int jp0   = (2 * j) & 127;

    const __half* orow =
        g_off + (((size_t)(b * H_ + ip)) * W_ + jp0) * OC_ + 2 * q + delta;
    const float off0 = __half2float(ldcg_h(orow));
    const float off1 = __half2float(ldcg_h(orow + OC_));

    float c0 = fminf(fmaxf(off0 + (float)i, 0.f), 127.f);
    float c1 = fminf(fmaxf(off1 + (float)j, 0.f), 127.f);

    const int lt0 = __float2int_rd(c0);
    const int lt1 = __float2int_rd(c1);
    const float fr0 = c0 - (float)lt0;
    const float fr1 = c1 - (float)lt1;
    const int rb0 = min(lt0 + 1, 127);
    const int rb1 = min(lt1 + 1, 127);

    const __half* xq = g_xh + (size_t)b * (H_ * W_ * C_) + q;
    const float v_lt = __half2float(__ldg(xq + (size_t)(lt0 * W_ + lt1) * C_));
    const float v_rb = __half2float(__ldg(xq + (size_t)(rb0 * W_ + rb1) * C_));
    const float v_lb = __half2float(__ldg(xq + (size_t)(lt0 * W_ + rb1) * C_));
    const float v_rt = __half2float(__ldg(xq + (size_t)(rb0 * W_ + lt1) * C_));

    const float vt = v_lt + (v_rt - v_lt) * fr0;
    const float vb = v_lb + (v_rb - v_lb) * fr0;
    return vt + (vb - vt) * fr1;
}

// 4 spatial positions per block -> 4 independent load chains (MLP x4).
__global__ void sample_kernel(float* __restrict__ out) {
    const int q    = threadIdx.x;
    const int bij0 = blockIdx.x * 4;          // j0 multiple of 4
    const int j0   = bij0 & 127;
    const int i    = (bij0 >> 7) & 127;
    const int b    = bij0 >> 14;

    float r[4];
#pragma unroll
    for (int t = 0; t < 4; ++t)
        r[t] = sample_one(b, i, j0 + t, q);
#pragma unroll
    for (int t = 0; t < 4; ++t)
        out[(size_t)(bij0 + t) * C_ + q] = r[t];
}

// ---------------- launch ----------------
extern "C" void kernel_launch(void* const* d_in, const int* in_sizes, int n_in,
                              void* d_out, int out_size) {
    const float* x    = (const float*)d_in[0];   // (8,128,128,256) f32
    const float* wgt  = (const float*)d_in[1];   // (3,3,256,512)  f32
    const float* bias = (const float*)d_in[2];   // (512,)         f32
    float* out = (float*)d_out;

    conv_x_f16<<<16384, 256>>>(x);
    conv_w_f16<<<576, 256>>>(wgt);

    cudaFuncSetAttribute(conv_hmma,
                         cudaFuncAttributeMaxDynamicSharedMemorySize, SMEM_BYTES);
    conv_hmma<<<dim3(4, 1024), 256, SMEM_BYTES>>>(bias);

    sample_kernel<<<(B_ * H_ * W_) / 4, 256>>>(out);
}